// round 1
// baseline (speedup 1.0000x reference)
#include <cuda_runtime.h>
#include <cstdint>

typedef unsigned long long ull;

// Rank-16 factors: psi[i*4096 + j] = sum_k Lt[i][k] * R[k][j]
__device__ __align__(16) float gLt[4096 * 16];   // [i][k] layout (transposed for kernel2)
__device__ __align__(16) float gR [16 * 4096];   // [k][j] layout

// Gate schedules (gate id, left-local wire u; acts on (u, u+1)).
// Left  = wires 0..11 (local bit of wire w is 11-w).
// Right = wires 12..23 (local bit of wire w is 23-w).
__constant__ short c_Lgi[22] = { 0, 1, 2, 3, 4, 5,  12,13,14,15,16,  23,24,25,26,27,28,  35,36,37,38,39 };
__constant__ short c_Rgi[22] = { 6, 7, 8, 9,10,11,  18,19,20,21,22,  29,30,31,32,33,34,  41,42,43,44,45 };
__constant__ short c_U  [22] = { 0, 2, 4, 6, 8,10,   1, 3, 5, 7, 9,   0, 2, 4, 6, 8,10,   1, 3, 5, 7, 9 };

// Apply 2-qubit gate on adjacent local wires (u, u+1). Strides: i0 -> 2^(11-u), i1 -> 2^(10-u).
// new[o0,o1] = sum_{i0,i1} G[i0,o0,i1,o1] * old[i0,i1];  G flat: [i0*8 + o0*4 + i1*2 + o1]
__device__ __forceinline__ void apply2(float* sv, const float* g, int u, int tid)
{
    const int b1 = 10 - u;          // lower inserted bit position
    const int s1 = 1 << b1;         // i1 stride
    const int s2 = s1 << 1;         // i0 stride
#pragma unroll 2
    for (int t = tid; t < 1024; t += 512) {
        int x = ((t >> b1) << (b1 + 2)) | (t & (s1 - 1));   // zeros at b1, b1+1
        float x00 = sv[x];
        float x01 = sv[x + s1];
        float x10 = sv[x + s2];
        float x11 = sv[x + s2 + s1];
        sv[x]           = g[0]*x00 + g[2]*x01 + g[ 8]*x10 + g[10]*x11;
        sv[x + s1]      = g[1]*x00 + g[3]*x01 + g[ 9]*x10 + g[11]*x11;
        sv[x + s2]      = g[4]*x00 + g[6]*x01 + g[12]*x10 + g[14]*x11;
        sv[x + s2 + s1] = g[5]*x00 + g[7]*x01 + g[13]*x10 + g[15]*x11;
    }
}

// Apply single-qubit 2x2 matrix m (layout m[o*2+i]) at local bit position `bit`.
__device__ __forceinline__ void apply1(float* sv, const float* m, int bit, int tid)
{
    const int s = 1 << bit;
#pragma unroll 4
    for (int t = tid; t < 2048; t += 512) {
        int x = ((t >> bit) << (bit + 1)) | (t & (s - 1));
        float y0 = sv[x], y1 = sv[x + s];
        sv[x]     = m[0]*y0 + m[1]*y1;
        sv[x + s] = m[2]*y0 + m[3]*y1;
    }
}

// 32 blocks: blocks 0..15 compute L_{ab} (k = a*4+b), 16..31 compute R_{ab}.
__global__ void __launch_bounds__(512) k_smallsim(const float* __restrict__ states,
                                                  const float* __restrict__ gates)
{
    __shared__ float sv[4096];
    __shared__ float gm[16];
    __shared__ float st[24];

    const int tid  = threadIdx.x;
    const int blk  = blockIdx.x;
    const int side = blk >> 4;          // 0 = left (wires 0..11), 1 = right (12..23)
    const int k    = blk & 15;
    const int a    = k >> 2;            // (i0,o0) of crossing gate 17:  i0=a>>1, o0=a&1
    const int b    = k & 3;             // (i0,o0) of crossing gate 40

    if (tid < 24) st[tid] = states[(side ? 24 : 0) + tid];
    __syncthreads();

    // Product-state init: local wire lw sits at bit (11-lw).
    for (int i = tid; i < 4096; i += 512) {
        float p = 1.f;
#pragma unroll
        for (int w = 0; w < 12; ++w) p *= st[2*w + ((i >> (11 - w)) & 1)];
        sv[i] = p;
    }

    // Single-qubit factor matrices, layout m[o*2+i].
    float m1[4], m2[4];
    if (side == 0) {
        // P_a = |o0><i0| on wire 11 (local bit 0)
        m1[0]=m1[1]=m1[2]=m1[3]=0.f;  m1[(a & 1)*2 + (a >> 1)] = 1.f;
        m2[0]=m2[1]=m2[2]=m2[3]=0.f;  m2[(b & 1)*2 + (b >> 1)] = 1.f;
    } else {
        // Q_a[o,i] = G17[i0,o0,i,o] on wire 12 (local bit 11)
        const float* g17 = gates + 17*16 + (a >> 1)*8 + (a & 1)*4;
        m1[0]=g17[0]; m1[1]=g17[2]; m1[2]=g17[1]; m1[3]=g17[3];
        const float* g40 = gates + 40*16 + (b >> 1)*8 + (b & 1)*4;
        m2[0]=g40[0]; m2[1]=g40[2]; m2[2]=g40[1]; m2[3]=g40[3];
    }

    for (int e = 0; e < 22; ++e) {
        __syncthreads();
        if (tid < 16) gm[tid] = gates[(side ? c_Rgi[e] : c_Lgi[e]) * 16 + tid];
        __syncthreads();
        apply2(sv, gm, c_U[e], tid);
        if (side == 0) {
            if (e == 10) { __syncthreads(); apply1(sv, m1, 0, tid); }   // P_a after left L0+L1
        } else {
            if (e == 5)  { __syncthreads(); apply1(sv, m1, 11, tid); }  // Q_a after right L0
            if (e == 16) { __syncthreads(); apply1(sv, m2, 11, tid); }  // Q'_b after right L1+L2
        }
    }
    if (side == 0) { __syncthreads(); apply1(sv, m2, 0, tid); }         // P'_b after left L3

    __syncthreads();
    if (side == 0) {
        for (int i = tid; i < 4096; i += 512) gLt[i*16 + k] = sv[i];
    } else {
        for (int j = tid; j < 4096; j += 512) gR[k*4096 + j] = sv[j];
    }
}

// Rank-16 expansion: out[i*4096 + j] = sum_k Lt[i][k] * R[k][j]
// Grid: (4, 128). Block = 256 threads. Each block: i-tile of 32, j-tile of 1024.
// Each thread owns one float4 column (4 j values) packed into two f32x2 accumulators.
__global__ void __launch_bounds__(256) k_expand(float4* __restrict__ out)
{
    __shared__ __align__(16) float sL[32 * 16];

    const int tid = threadIdx.x;
    const int jb  = blockIdx.x;     // 0..3   -> j base = jb*1024
    const int ib  = blockIdx.y;     // 0..127 -> i base = ib*32

    // Load L tile [32][16] (512 floats) cooperatively.
    ((float2*)sL)[tid] = ((const float2*)(gLt + ib * 512))[tid];

    // Preload this thread's R column: 16 x float4, packed as f32x2 pairs.
    const float4* gR4 = reinterpret_cast<const float4*>(gR);
    const int jq = jb * 256 + tid;              // float4 column index, 0..1023
    ull rlo[16], rhi[16];
#pragma unroll
    for (int kk = 0; kk < 16; ++kk) {
        float4 r = gR4[kk * 1024 + jq];
        asm("mov.b64 %0,{%1,%2};" : "=l"(rlo[kk]) : "f"(r.x), "f"(r.y));
        asm("mov.b64 %0,{%1,%2};" : "=l"(rhi[kk]) : "f"(r.z), "f"(r.w));
    }
    __syncthreads();

    const float4* sL4 = reinterpret_cast<const float4*>(sL);
#pragma unroll 4
    for (int ii = 0; ii < 32; ++ii) {
        ull a0 = 0ull, a1 = 0ull;               // packed (0.f, 0.f)
#pragma unroll
        for (int kq = 0; kq < 4; ++kq) {
            float4 l4 = sL4[ii * 4 + kq];
            ull lp;
            asm("mov.b64 %0,{%1,%1};" : "=l"(lp) : "f"(l4.x));
            asm("fma.rn.f32x2 %0, %1, %2, %0;" : "+l"(a0) : "l"(lp), "l"(rlo[kq*4 + 0]));
            asm("fma.rn.f32x2 %0, %1, %2, %0;" : "+l"(a1) : "l"(lp), "l"(rhi[kq*4 + 0]));
            asm("mov.b64 %0,{%1,%1};" : "=l"(lp) : "f"(l4.y));
            asm("fma.rn.f32x2 %0, %1, %2, %0;" : "+l"(a0) : "l"(lp), "l"(rlo[kq*4 + 1]));
            asm("fma.rn.f32x2 %0, %1, %2, %0;" : "+l"(a1) : "l"(lp), "l"(rhi[kq*4 + 1]));
            asm("mov.b64 %0,{%1,%1};" : "=l"(lp) : "f"(l4.z));
            asm("fma.rn.f32x2 %0, %1, %2, %0;" : "+l"(a0) : "l"(lp), "l"(rlo[kq*4 + 2]));
            asm("fma.rn.f32x2 %0, %1, %2, %0;" : "+l"(a1) : "l"(lp), "l"(rhi[kq*4 + 2]));
            asm("mov.b64 %0,{%1,%1};" : "=l"(lp) : "f"(l4.w));
            asm("fma.rn.f32x2 %0, %1, %2, %0;" : "+l"(a0) : "l"(lp), "l"(rlo[kq*4 + 3]));
            asm("fma.rn.f32x2 %0, %1, %2, %0;" : "+l"(a1) : "l"(lp), "l"(rhi[kq*4 + 3]));
        }
        float o0, o1, o2, o3;
        asm("mov.b64 {%0,%1}, %2;" : "=f"(o0), "=f"(o1) : "l"(a0));
        asm("mov.b64 {%0,%1}, %2;" : "=f"(o2), "=f"(o3) : "l"(a1));
        out[(ib * 32 + ii) * 1024 + jq] = make_float4(o0, o1, o2, o3);
    }
}

extern "C" void kernel_launch(void* const* d_in, const int* in_sizes, int n_in,
                              void* d_out, int out_size)
{
    const float* states = (const float*)d_in[0];   // (24, 2) f32
    const float* gates  = (const float*)d_in[1];   // (46, 2,2,2,2) f32
    (void)in_sizes; (void)n_in; (void)out_size;    // gate_wires (d_in[2]) is the fixed brickwork

    k_smallsim<<<32, 512>>>(states, gates);
    k_expand<<<dim3(4, 128), 256>>>((float4*)d_out);
}

// round 2
// speedup vs baseline: 1.0231x; 1.0231x over previous
#include <cuda_runtime.h>
#include <cstdint>

typedef unsigned long long ull;

// Rank-16 factors: psi[i*4096 + j] = sum_k Lt[i][k] * R[k][j]
__device__ __align__(16) float gLt[4096 * 16];   // [i][k] layout (transposed for kernel2)
__device__ __align__(16) float gR [16 * 4096];   // [k][j] layout

// Gate schedules (gate id, left-local wire u; acts on (u, u+1)).
// Left  = wires 0..11 (local bit of wire w is 11-w).
// Right = wires 12..23 (local bit of wire w is 23-w).
__constant__ short c_Lgi[22] = { 0, 1, 2, 3, 4, 5,  12,13,14,15,16,  23,24,25,26,27,28,  35,36,37,38,39 };
__constant__ short c_Rgi[22] = { 6, 7, 8, 9,10,11,  18,19,20,21,22,  29,30,31,32,33,34,  41,42,43,44,45 };
__constant__ short c_U  [22] = { 0, 2, 4, 6, 8,10,   1, 3, 5, 7, 9,   0, 2, 4, 6, 8,10,   1, 3, 5, 7, 9 };

// Apply 2-qubit gate on adjacent local wires (u, u+1). Strides: i0 -> 2^(11-u), i1 -> 2^(10-u).
// new[o0,o1] = sum_{i0,i1} G[i0,o0,i1,o1] * old[i0,i1];  G flat: [i0*8 + o0*4 + i1*2 + o1]
__device__ __forceinline__ void apply2(float* sv, const float* g, int u, int tid)
{
    const int b1 = 10 - u;          // lower inserted bit position
    const int s1 = 1 << b1;         // i1 stride
    const int s2 = s1 << 1;         // i0 stride
#pragma unroll 2
    for (int t = tid; t < 1024; t += 512) {
        int x = ((t >> b1) << (b1 + 2)) | (t & (s1 - 1));   // zeros at b1, b1+1
        float x00 = sv[x];
        float x01 = sv[x + s1];
        float x10 = sv[x + s2];
        float x11 = sv[x + s2 + s1];
        sv[x]           = g[0]*x00 + g[2]*x01 + g[ 8]*x10 + g[10]*x11;
        sv[x + s1]      = g[1]*x00 + g[3]*x01 + g[ 9]*x10 + g[11]*x11;
        sv[x + s2]      = g[4]*x00 + g[6]*x01 + g[12]*x10 + g[14]*x11;
        sv[x + s2 + s1] = g[5]*x00 + g[7]*x01 + g[13]*x10 + g[15]*x11;
    }
}

// Apply single-qubit 2x2 matrix m (layout m[o*2+i]) at local bit position `bit`.
__device__ __forceinline__ void apply1(float* sv, const float* m, int bit, int tid)
{
    const int s = 1 << bit;
#pragma unroll 4
    for (int t = tid; t < 2048; t += 512) {
        int x = ((t >> bit) << (bit + 1)) | (t & (s - 1));
        float y0 = sv[x], y1 = sv[x + s];
        sv[x]     = m[0]*y0 + m[1]*y1;
        sv[x + s] = m[2]*y0 + m[3]*y1;
    }
}

// 32 blocks: blocks 0..15 compute L_{ab} (k = a*4+b), 16..31 compute R_{ab}.
__global__ void __launch_bounds__(512) k_smallsim(const float* __restrict__ states,
                                                  const float* __restrict__ gates)
{
    __shared__ float sv[4096];
    __shared__ float gm[16];
    __shared__ float st[24];

    const int tid  = threadIdx.x;
    const int blk  = blockIdx.x;
    const int side = blk >> 4;          // 0 = left (wires 0..11), 1 = right (12..23)
    const int k    = blk & 15;
    const int a    = k >> 2;            // (i0,o0) of crossing gate 17:  i0=a>>1, o0=a&1
    const int b    = k & 3;             // (i0,o0) of crossing gate 40

    if (tid < 24) st[tid] = states[(side ? 24 : 0) + tid];
    __syncthreads();

    // Product-state init: local wire lw sits at bit (11-lw).
    for (int i = tid; i < 4096; i += 512) {
        float p = 1.f;
#pragma unroll
        for (int w = 0; w < 12; ++w) p *= st[2*w + ((i >> (11 - w)) & 1)];
        sv[i] = p;
    }

    // Single-qubit factor matrices, layout m[o*2+i].
    float m1[4], m2[4];
    if (side == 0) {
        // P_a = |o0><i0| on wire 11 (local bit 0)
        m1[0]=m1[1]=m1[2]=m1[3]=0.f;  m1[(a & 1)*2 + (a >> 1)] = 1.f;
        m2[0]=m2[1]=m2[2]=m2[3]=0.f;  m2[(b & 1)*2 + (b >> 1)] = 1.f;
    } else {
        // Q_a[o,i] = G17[i0,o0,i,o] on wire 12 (local bit 11)
        const float* g17 = gates + 17*16 + (a >> 1)*8 + (a & 1)*4;
        m1[0]=g17[0]; m1[1]=g17[2]; m1[2]=g17[1]; m1[3]=g17[3];
        const float* g40 = gates + 40*16 + (b >> 1)*8 + (b & 1)*4;
        m2[0]=g40[0]; m2[1]=g40[2]; m2[2]=g40[1]; m2[3]=g40[3];
    }

    for (int e = 0; e < 22; ++e) {
        __syncthreads();
        if (tid < 16) gm[tid] = gates[(side ? c_Rgi[e] : c_Lgi[e]) * 16 + tid];
        __syncthreads();
        apply2(sv, gm, c_U[e], tid);
        if (side == 0) {
            if (e == 10) { __syncthreads(); apply1(sv, m1, 0, tid); }   // P_a after left L0+L1
        } else {
            if (e == 5)  { __syncthreads(); apply1(sv, m1, 11, tid); }  // Q_a after right L0
            if (e == 16) { __syncthreads(); apply1(sv, m2, 11, tid); }  // Q'_b after right L1+L2
        }
    }
    if (side == 0) { __syncthreads(); apply1(sv, m2, 0, tid); }         // P'_b after left L3

    __syncthreads();
    if (side == 0) {
        for (int i = tid; i < 4096; i += 512) gLt[i*16 + k] = sv[i];
    } else {
        for (int j = tid; j < 4096; j += 512) gR[k*4096 + j] = sv[j];
    }
}

// Rank-16 expansion: out[i*4096 + j] = sum_k Lt[i][k] * R[k][j]
// Grid: (4, 128). Block = 256 threads. Each block: i-tile of 32, j-tile of 1024.
// Each thread owns one float4 column (4 j values) packed into two f32x2 accumulators.
__global__ void __launch_bounds__(256) k_expand(float4* __restrict__ out)
{
    __shared__ __align__(16) float sL[32 * 16];

    const int tid = threadIdx.x;
    const int jb  = blockIdx.x;     // 0..3   -> j base = jb*1024
    const int ib  = blockIdx.y;     // 0..127 -> i base = ib*32

    // Load L tile [32][16] (512 floats) cooperatively.
    ((float2*)sL)[tid] = ((const float2*)(gLt + ib * 512))[tid];

    // Preload this thread's R column: 16 x float4, packed as f32x2 pairs.
    const float4* gR4 = reinterpret_cast<const float4*>(gR);
    const int jq = jb * 256 + tid;              // float4 column index, 0..1023
    ull rlo[16], rhi[16];
#pragma unroll
    for (int kk = 0; kk < 16; ++kk) {
        float4 r = gR4[kk * 1024 + jq];
        asm("mov.b64 %0,{%1,%2};" : "=l"(rlo[kk]) : "f"(r.x), "f"(r.y));
        asm("mov.b64 %0,{%1,%2};" : "=l"(rhi[kk]) : "f"(r.z), "f"(r.w));
    }
    __syncthreads();

    const float4* sL4 = reinterpret_cast<const float4*>(sL);
#pragma unroll 4
    for (int ii = 0; ii < 32; ++ii) {
        ull a0 = 0ull, a1 = 0ull;               // packed (0.f, 0.f)
#pragma unroll
        for (int kq = 0; kq < 4; ++kq) {
            float4 l4 = sL4[ii * 4 + kq];
            ull lp;
            asm("mov.b64 %0,{%1,%1};" : "=l"(lp) : "f"(l4.x));
            asm("fma.rn.f32x2 %0, %1, %2, %0;" : "+l"(a0) : "l"(lp), "l"(rlo[kq*4 + 0]));
            asm("fma.rn.f32x2 %0, %1, %2, %0;" : "+l"(a1) : "l"(lp), "l"(rhi[kq*4 + 0]));
            asm("mov.b64 %0,{%1,%1};" : "=l"(lp) : "f"(l4.y));
            asm("fma.rn.f32x2 %0, %1, %2, %0;" : "+l"(a0) : "l"(lp), "l"(rlo[kq*4 + 1]));
            asm("fma.rn.f32x2 %0, %1, %2, %0;" : "+l"(a1) : "l"(lp), "l"(rhi[kq*4 + 1]));
            asm("mov.b64 %0,{%1,%1};" : "=l"(lp) : "f"(l4.z));
            asm("fma.rn.f32x2 %0, %1, %2, %0;" : "+l"(a0) : "l"(lp), "l"(rlo[kq*4 + 2]));
            asm("fma.rn.f32x2 %0, %1, %2, %0;" : "+l"(a1) : "l"(lp), "l"(rhi[kq*4 + 2]));
            asm("mov.b64 %0,{%1,%1};" : "=l"(lp) : "f"(l4.w));
            asm("fma.rn.f32x2 %0, %1, %2, %0;" : "+l"(a0) : "l"(lp), "l"(rlo[kq*4 + 3]));
            asm("fma.rn.f32x2 %0, %1, %2, %0;" : "+l"(a1) : "l"(lp), "l"(rhi[kq*4 + 3]));
        }
        float o0, o1, o2, o3;
        asm("mov.b64 {%0,%1}, %2;" : "=f"(o0), "=f"(o1) : "l"(a0));
        asm("mov.b64 {%0,%1}, %2;" : "=f"(o2), "=f"(o3) : "l"(a1));
        out[(ib * 32 + ii) * 1024 + jq] = make_float4(o0, o1, o2, o3);
    }
}

extern "C" void kernel_launch(void* const* d_in, const int* in_sizes, int n_in,
                              void* d_out, int out_size)
{
    const float* states = (const float*)d_in[0];   // (24, 2) f32
    const float* gates  = (const float*)d_in[1];   // (46, 2,2,2,2) f32
    (void)in_sizes; (void)n_in; (void)out_size;    // gate_wires (d_in[2]) is the fixed brickwork

    k_smallsim<<<32, 512>>>(states, gates);
    k_expand<<<dim3(4, 128), 256>>>((float4*)d_out);
}

// round 3
// speedup vs baseline: 1.4558x; 1.4230x over previous
#include <cuda_runtime.h>
#include <cstdint>

typedef unsigned long long ull;

// Rank-16 factors with parity compaction:
//   psi[i*4096 + j] = sum_{m=0..7} Lt[i][m] * R[(i&1)*8 + m][j]
// (left factor L_{ab} is zero unless i&1 == b&1; m = a*2 + (b>>1))
__device__ __align__(16) float gLt[4096 * 8];    // [i][m] compacted
__device__ __align__(16) float gR [16 * 4096];   // [p*8+m][j]

// Gate schedules (gate id, left-local wire u; gate acts on local wires (u, u+1)).
__constant__ short c_Lgi[22] = { 0, 1, 2, 3, 4, 5,  12,13,14,15,16,  23,24,25,26,27,28,  35,36,37,38,39 };
__constant__ short c_Rgi[22] = { 6, 7, 8, 9,10,11,  18,19,20,21,22,  29,30,31,32,33,34,  41,42,43,44,45 };
__constant__ short c_U  [22] = { 0, 2, 4, 6, 8,10,   1, 3, 5, 7, 9,   0, 2, 4, 6, 8,10,   1, 3, 5, 7, 9 };

// Scalar single-qubit 2x2 (m layout m[o*2+i]) at local bit position `bit`.
__device__ __forceinline__ void apply1(float* sv, const float* m, int bit, int tid)
{
    const int s = 1 << bit;
#pragma unroll 4
    for (int t = tid; t < 2048; t += 512) {
        int x = ((t >> bit) << (bit + 1)) | (t & (s - 1));
        float y0 = sv[x], y1 = sv[x + s];
        sv[x]     = m[0]*y0 + m[1]*y1;
        sv[x + s] = m[2]*y0 + m[3]*y1;
    }
}

// 32 blocks: 0..15 compute compacted L_{ab}, 16..31 compute R_{ab}.
__global__ void __launch_bounds__(512) k_smallsim(const float* __restrict__ states,
                                                  const float* __restrict__ gates)
{
    __shared__ __align__(16) float sv[4096];
    __shared__ __align__(16) float gsh[352];   // all 22 gates for this side
    __shared__ float st[24];

    const int tid  = threadIdx.x;
    const int blk  = blockIdx.x;
    const int side = blk >> 4;
    const int k    = blk & 15;
    const int a    = k >> 2;
    const int b    = k & 3;

    // Batched preload of ALL 22 gates (one LDG round, not 22 serialized ones).
    if (tid < 352) {
        int e  = tid >> 4;
        int gi = side ? c_Rgi[e] : c_Lgi[e];
        gsh[tid] = gates[gi * 16 + (tid & 15)];
    }
    if (tid >= 488) st[tid - 488] = states[(side ? 24 : 0) + tid - 488];

    // Single-qubit crossing-gate factors (global loads overlap with the barrier).
    float m1[4], m2[4];
    if (side == 0) {
        m1[0]=m1[1]=m1[2]=m1[3]=0.f;  m1[(a & 1)*2 + (a >> 1)] = 1.f;
        m2[0]=m2[1]=m2[2]=m2[3]=0.f;  m2[(b & 1)*2 + (b >> 1)] = 1.f;
    } else {
        const float* g17 = gates + 17*16 + (a >> 1)*8 + (a & 1)*4;
        m1[0]=g17[0]; m1[1]=g17[2]; m1[2]=g17[1]; m1[3]=g17[3];
        const float* g40 = gates + 40*16 + (b >> 1)*8 + (b & 1)*4;
        m2[0]=g40[0]; m2[1]=g40[2]; m2[2]=g40[1]; m2[3]=g40[3];
    }
    __syncthreads();

    // Product-state init: hoist the 9 low-bit factors (invariant across q).
    {
        float plow = 1.f;
#pragma unroll
        for (int w = 3; w < 12; ++w) plow *= st[2*w + ((tid >> (11 - w)) & 1)];
#pragma unroll
        for (int q = 0; q < 8; ++q) {
            int i = q * 512 + tid;
            float p = plow;
#pragma unroll
            for (int w = 0; w < 3; ++w) p *= st[2*w + ((i >> (11 - w)) & 1)];
            sv[i] = p;
        }
    }
    __syncthreads();

    // 22 two-qubit gates, ONE barrier per gate, vectorized butterflies.
#pragma unroll
    for (int e = 0; e < 22; ++e) {
        const float* g = gsh + e * 16;
        const float4 g0 = *(const float4*)(g);
        const float4 g1 = *(const float4*)(g + 4);
        const float4 g2 = *(const float4*)(g + 8);
        const float4 g3 = *(const float4*)(g + 12);
        const int u = c_U[e];

        if (u == 10) {
            // b1 = 0: one butterfly = 4 contiguous floats -> float4, 2 per thread.
#pragma unroll
            for (int q = 0; q < 2; ++q) {
                int x = (q * 512 + tid) * 4;
                float4 v = *(float4*)&sv[x];
                float4 o;
                o.x = g0.x*v.x + g0.z*v.y + g2.x*v.z + g2.z*v.w;
                o.y = g0.y*v.x + g0.w*v.y + g2.y*v.z + g2.w*v.w;
                o.z = g1.x*v.x + g1.z*v.y + g3.x*v.z + g3.z*v.w;
                o.w = g1.y*v.x + g1.w*v.y + g3.y*v.z + g3.w*v.w;
                *(float4*)&sv[x] = o;
            }
        } else {
            // b1 >= 1: two adjacent butterflies per thread via float2.
            const int b1 = 10 - u, s1 = 1 << b1, s2 = s1 << 1;
            const int t  = tid * 2;
            const int x  = ((t >> b1) << (b1 + 2)) | (t & (s1 - 1));
            float2 v00 = *(float2*)&sv[x];
            float2 v01 = *(float2*)&sv[x + s1];
            float2 v10 = *(float2*)&sv[x + s2];
            float2 v11 = *(float2*)&sv[x + s2 + s1];
            float2 o00, o01, o10, o11;
            o00.x = g0.x*v00.x + g0.z*v01.x + g2.x*v10.x + g2.z*v11.x;
            o00.y = g0.x*v00.y + g0.z*v01.y + g2.x*v10.y + g2.z*v11.y;
            o01.x = g0.y*v00.x + g0.w*v01.x + g2.y*v10.x + g2.w*v11.x;
            o01.y = g0.y*v00.y + g0.w*v01.y + g2.y*v10.y + g2.w*v11.y;
            o10.x = g1.x*v00.x + g1.z*v01.x + g3.x*v10.x + g3.z*v11.x;
            o10.y = g1.x*v00.y + g1.z*v01.y + g3.x*v10.y + g3.z*v11.y;
            o11.x = g1.y*v00.x + g1.w*v01.x + g3.y*v10.x + g3.w*v11.x;
            o11.y = g1.y*v00.y + g1.w*v01.y + g3.y*v10.y + g3.w*v11.y;
            *(float2*)&sv[x]           = o00;
            *(float2*)&sv[x + s1]      = o01;
            *(float2*)&sv[x + s2]      = o10;
            *(float2*)&sv[x + s2 + s1] = o11;
        }

        if (side == 0) {
            if (e == 10) { __syncthreads(); apply1(sv, m1, 0, tid); }
        } else {
            if (e == 5)  { __syncthreads(); apply1(sv, m1, 11, tid); }
            if (e == 16) { __syncthreads(); apply1(sv, m2, 11, tid); }
        }
        __syncthreads();
    }

    if (side == 0) {
        apply1(sv, m2, 0, tid);            // P'_b: zeros out bit0 != (b&1)
        __syncthreads();
        // Compacted store: only the nonzero parity slice; m = a*2 + (b>>1).
        const int m = a * 2 + (b >> 1);
        const int p = b & 1;
#pragma unroll
        for (int t = tid; t < 2048; t += 512) {
            int i = 2 * t + p;
            gLt[i * 8 + m] = sv[i];
        }
    } else {
        const int m = a * 2 + (b >> 1);
        const int p = b & 1;
#pragma unroll
        for (int j = tid; j < 4096; j += 512)
            gR[(p * 8 + m) * 4096 + j] = sv[j];
    }
}

// Rank-8-per-parity expansion: out[i*4096+j] = sum_m Lt[i][m] * R[(i&1)*8+m][j]
// Grid (4, 128), block 256. Block tile: 32 i-rows x 1024 j. Thread: 1 float4 column.
__global__ void __launch_bounds__(256) k_expand(float4* __restrict__ out)
{
    __shared__ __align__(16) ull sLd[32 * 8];   // L tile, pre-duplicated {v,v} packs

    const int tid = threadIdx.x;
    const int jb  = blockIdx.x;
    const int ib  = blockIdx.y;

    // Load + duplicate L tile (256 floats, one per thread).
    {
        float v = gLt[ib * 256 + tid];
        ull p;
        asm("mov.b64 %0,{%1,%1};" : "=l"(p) : "f"(v));
        sLd[tid] = p;
    }

    // Preload R column for both parities: 16 x float4 -> 32 packed ulls.
    const float4* gR4 = reinterpret_cast<const float4*>(gR);
    const int jq = jb * 256 + tid;
    ull re_lo[8], re_hi[8], ro_lo[8], ro_hi[8];
#pragma unroll
    for (int m = 0; m < 8; ++m) {
        float4 r = gR4[m * 1024 + jq];                 // parity 0
        asm("mov.b64 %0,{%1,%2};" : "=l"(re_lo[m]) : "f"(r.x), "f"(r.y));
        asm("mov.b64 %0,{%1,%2};" : "=l"(re_hi[m]) : "f"(r.z), "f"(r.w));
        float4 s = gR4[(8 + m) * 1024 + jq];           // parity 1
        asm("mov.b64 %0,{%1,%2};" : "=l"(ro_lo[m]) : "f"(s.x), "f"(s.y));
        asm("mov.b64 %0,{%1,%2};" : "=l"(ro_hi[m]) : "f"(s.z), "f"(s.w));
    }
    __syncthreads();

    const ulonglong2* sL2 = reinterpret_cast<const ulonglong2*>(sLd);
#pragma unroll 4
    for (int ii = 0; ii < 32; ii += 2) {
        ull a0 = 0ull, a1 = 0ull, b0 = 0ull, b1 = 0ull;   // 4 independent chains
        const ulonglong2* L0 = sL2 + ii * 4;              // even row (parity 0)
        const ulonglong2* L1 = L0 + 4;                    // odd row  (parity 1)
#pragma unroll
        for (int mq = 0; mq < 4; ++mq) {
            ulonglong2 le = L0[mq];
            ulonglong2 lo = L1[mq];
            asm("fma.rn.f32x2 %0, %1, %2, %0;" : "+l"(a0) : "l"(le.x), "l"(re_lo[2*mq]));
            asm("fma.rn.f32x2 %0, %1, %2, %0;" : "+l"(a1) : "l"(le.x), "l"(re_hi[2*mq]));
            asm("fma.rn.f32x2 %0, %1, %2, %0;" : "+l"(b0) : "l"(lo.x), "l"(ro_lo[2*mq]));
            asm("fma.rn.f32x2 %0, %1, %2, %0;" : "+l"(b1) : "l"(lo.x), "l"(ro_hi[2*mq]));
            asm("fma.rn.f32x2 %0, %1, %2, %0;" : "+l"(a0) : "l"(le.y), "l"(re_lo[2*mq+1]));
            asm("fma.rn.f32x2 %0, %1, %2, %0;" : "+l"(a1) : "l"(le.y), "l"(re_hi[2*mq+1]));
            asm("fma.rn.f32x2 %0, %1, %2, %0;" : "+l"(b0) : "l"(lo.y), "l"(ro_lo[2*mq+1]));
            asm("fma.rn.f32x2 %0, %1, %2, %0;" : "+l"(b1) : "l"(lo.y), "l"(ro_hi[2*mq+1]));
        }
        float e0, e1, e2, e3, o0, o1, o2, o3;
        asm("mov.b64 {%0,%1}, %2;" : "=f"(e0), "=f"(e1) : "l"(a0));
        asm("mov.b64 {%0,%1}, %2;" : "=f"(e2), "=f"(e3) : "l"(a1));
        asm("mov.b64 {%0,%1}, %2;" : "=f"(o0), "=f"(o1) : "l"(b0));
        asm("mov.b64 {%0,%1}, %2;" : "=f"(o2), "=f"(o3) : "l"(b1));
        out[(ib * 32 + ii)     * 1024 + jq] = make_float4(e0, e1, e2, e3);
        out[(ib * 32 + ii + 1) * 1024 + jq] = make_float4(o0, o1, o2, o3);
    }
}

extern "C" void kernel_launch(void* const* d_in, const int* in_sizes, int n_in,
                              void* d_out, int out_size)
{
    const float* states = (const float*)d_in[0];   // (24, 2) f32
    const float* gates  = (const float*)d_in[1];   // (46, 2,2,2,2) f32
    (void)in_sizes; (void)n_in; (void)out_size;

    k_smallsim<<<32, 512>>>(states, gates);
    k_expand<<<dim3(4, 128), 256>>>((float4*)d_out);
}

// round 5
// speedup vs baseline: 1.5838x; 1.0879x over previous
#include <cuda_runtime.h>
#include <cstdint>

typedef unsigned long long ull;

// Rank-16 factors with parity compaction:
//   psi[i*4096 + j] = sum_{m=0..7} Lt[i][m] * R[(i&1)*8 + m][j]
__device__ __align__(16) float gLt[4096 * 8];    // [i][m]
__device__ __align__(16) float gR [16 * 4096];   // [p*8+m][j]

// Gate id schedules per side, ordered by layer then wire.
// e:        0  1  2  3  4  5   6  7  8  9 10   11 12 13 14 15 16   17 18 19 20 21
// b1=10-u: 10  8  6  4  2  0   9  7  5  3  1   10  8  6  4  2  0    9  7  5  3  1
__constant__ short c_Lgi[22] = { 0, 1, 2, 3, 4, 5,  12,13,14,15,16,  23,24,25,26,27,28,  35,36,37,38,39 };
__constant__ short c_Rgi[22] = { 6, 7, 8, 9,10,11,  18,19,20,21,22,  29,30,31,32,33,34,  41,42,43,44,45 };

// Bank-conflict-killing smem swizzle: float-index bits 3,4 ^= bits 7,8.
__device__ __forceinline__ int swz(int i) { return i ^ (((i >> 7) & 3) << 3); }

// ---- in-register gate applications on a 16-amp tile (local bits 0..3) ----
// gate layout g[i0*8 + o0*4 + i1*2 + o1]; i0 = higher bit of the pair.

__device__ __forceinline__ void gate_high(float* v, const float* g) {   // bits (2,3)
#pragma unroll
    for (int s = 0; s < 4; ++s) {
        float x00 = v[s], x01 = v[s|4], x10 = v[s|8], x11 = v[s|12];
        v[s]    = g[0]*x00 + g[2]*x01 + g[ 8]*x10 + g[10]*x11;
        v[s|4]  = g[1]*x00 + g[3]*x01 + g[ 9]*x10 + g[11]*x11;
        v[s|8]  = g[4]*x00 + g[6]*x01 + g[12]*x10 + g[14]*x11;
        v[s|12] = g[5]*x00 + g[7]*x01 + g[13]*x10 + g[15]*x11;
    }
}
__device__ __forceinline__ void gate_low(float* v, const float* g) {    // bits (0,1)
#pragma unroll
    for (int s = 0; s < 16; s += 4) {
        float x00 = v[s], x01 = v[s+1], x10 = v[s+2], x11 = v[s+3];
        v[s]   = g[0]*x00 + g[2]*x01 + g[ 8]*x10 + g[10]*x11;
        v[s+1] = g[1]*x00 + g[3]*x01 + g[ 9]*x10 + g[11]*x11;
        v[s+2] = g[4]*x00 + g[6]*x01 + g[12]*x10 + g[14]*x11;
        v[s+3] = g[5]*x00 + g[7]*x01 + g[13]*x10 + g[15]*x11;
    }
}
__device__ __forceinline__ void gate_mid(float* v, const float* g) {    // bits (1,2)
#pragma unroll
    for (int s0 = 0; s0 < 16; s0 += 8)
#pragma unroll
        for (int b0 = 0; b0 < 2; ++b0) {
            int s = s0 | b0;
            float x00 = v[s], x01 = v[s|2], x10 = v[s|4], x11 = v[s|6];
            v[s]   = g[0]*x00 + g[2]*x01 + g[ 8]*x10 + g[10]*x11;
            v[s|2] = g[1]*x00 + g[3]*x01 + g[ 9]*x10 + g[11]*x11;
            v[s|4] = g[4]*x00 + g[6]*x01 + g[12]*x10 + g[14]*x11;
            v[s|6] = g[5]*x00 + g[7]*x01 + g[13]*x10 + g[15]*x11;
        }
}
// single-qubit 2x2 m[o*2+i] on local bit 0 / bit 3
__device__ __forceinline__ void op1_b0(float* v, const float* m) {
#pragma unroll
    for (int s = 0; s < 16; s += 2) {
        float y0 = v[s], y1 = v[s+1];
        v[s]   = m[0]*y0 + m[1]*y1;
        v[s+1] = m[2]*y0 + m[3]*y1;
    }
}
__device__ __forceinline__ void op1_b3(float* v, const float* m) {
#pragma unroll
    for (int s = 0; s < 8; ++s) {
        float y0 = v[s], y1 = v[s|8];
        v[s]   = m[0]*y0 + m[1]*y1;
        v[s|8] = m[2]*y0 + m[3]*y1;
    }
}

// ---- tile exchange through swizzled smem; tile bits T0..T0+3 ----
template<int T0>
__device__ __forceinline__ void store_tile(float* sv, const float* v, int tid) {
    if constexpr (T0 == 0) {
        const int base = tid << 4;
#pragma unroll
        for (int c = 0; c < 4; ++c)
            *(float4*)&sv[swz(base + c*4)] = make_float4(v[4*c], v[4*c+1], v[4*c+2], v[4*c+3]);
    } else {
        const int base = ((tid >> T0) << (T0 + 4)) | (tid & ((1 << T0) - 1));
#pragma unroll
        for (int k = 0; k < 16; ++k) sv[swz(base + (k << T0))] = v[k];
    }
}
template<int T0>
__device__ __forceinline__ void load_tile(const float* sv, float* v, int tid) {
    if constexpr (T0 == 0) {
        const int base = tid << 4;
#pragma unroll
        for (int c = 0; c < 4; ++c) {
            float4 t = *(const float4*)&sv[swz(base + c*4)];
            v[4*c] = t.x; v[4*c+1] = t.y; v[4*c+2] = t.z; v[4*c+3] = t.w;
        }
    } else {
        const int base = ((tid >> T0) << (T0 + 4)) | (tid & ((1 << T0) - 1));
#pragma unroll
        for (int k = 0; k < 16; ++k) v[k] = sv[swz(base + (k << T0))];
    }
}

__device__ __forceinline__ void load_gate(float* g, const float* gsh) {
#pragma unroll
    for (int c = 0; c < 4; ++c) {
        float4 t = *(const float4*)(gsh + 4*c);
        g[4*c] = t.x; g[4*c+1] = t.y; g[4*c+2] = t.z; g[4*c+3] = t.w;
    }
}

// 32 blocks: 0..15 -> L_{ab} (k=a*4+b), 16..31 -> R_{ab}. 256 threads, 16 amps each.
__global__ void __launch_bounds__(256) k_smallsim(const float* __restrict__ states,
                                                  const float* __restrict__ gates)
{
    __shared__ __align__(16) float sv[4096];
    __shared__ __align__(16) float gsh[352];
    __shared__ float st[24];

    const int tid  = threadIdx.x;
    const int blk  = blockIdx.x;
    const int side = blk >> 4;
    const int k    = blk & 15;
    const int a    = k >> 2;
    const int b    = k & 3;

    // FIX (R4 bug): 352 gate floats, 256 threads -> strided loop, not a single guarded store.
#pragma unroll
    for (int t = tid; t < 352; t += 256) {
        int e = t >> 4;
        int gi = side ? c_Rgi[e] : c_Lgi[e];
        gsh[t] = gates[gi * 16 + (t & 15)];
    }
    if (tid >= 232) st[tid - 232] = states[(side ? 24 : 0) + tid - 232];

    // crossing-gate single-qubit factors, layout m[o*2+i]
    float m1[4], m2[4];
    if (side == 0) {
        m1[0]=m1[1]=m1[2]=m1[3]=0.f;  m1[(a & 1)*2 + (a >> 1)] = 1.f;   // P_a on bit 0
        m2[0]=m2[1]=m2[2]=m2[3]=0.f;  m2[(b & 1)*2 + (b >> 1)] = 1.f;   // P'_b on bit 0
    } else {
        const float* g17 = gates + 17*16 + (a >> 1)*8 + (a & 1)*4;       // Q_a on bit 11
        m1[0]=g17[0]; m1[1]=g17[2]; m1[2]=g17[1]; m1[3]=g17[3];
        const float* g40 = gates + 40*16 + (b >> 1)*8 + (b & 1)*4;       // Q'_b on bit 11
        m2[0]=g40[0]; m2[1]=g40[2]; m2[2]=g40[1]; m2[3]=g40[3];
    }
    __syncthreads();

    // Init directly into P1's register tile (bits 8..11 local; bits 0..7 = tid).
    float v[16];
    {
        float pb = 1.f;
#pragma unroll
        for (int w = 4; w < 12; ++w) pb *= st[2*w + ((tid >> (11 - w)) & 1)];
#pragma unroll
        for (int kk = 0; kk < 16; ++kk) {
            float p = pb;
#pragma unroll
            for (int w = 0; w < 4; ++w) p *= st[2*w + ((kk >> (3 - w)) & 1)];
            v[kk] = p;
        }
    }

    float g0[16], g1[16], g2[16];

    // P1: tile 8-11 — e0 (bits 11,10), e1 (9,8); right: Q_a on bit 11 (tile bit 3)
    load_gate(g0, gsh + 0*16); load_gate(g1, gsh + 1*16);
    gate_high(v, g0); gate_low(v, g1);
    if (side) op1_b3(v, m1);
    store_tile<8>(sv, v, tid); __syncthreads();

    // P2: tile 4-7 — e2 (7,6), e3 (5,4)
    load_tile<4>(sv, v, tid);
    load_gate(g0, gsh + 2*16); load_gate(g1, gsh + 3*16);
    gate_high(v, g0); gate_low(v, g1);
    store_tile<4>(sv, v, tid); __syncthreads();

    // P3: tile 0-3 — e4 (3,2), e5 (1,0), then layer-1 e10 (2,1); left: P_a on bit 0
    load_tile<0>(sv, v, tid);
    load_gate(g0, gsh + 4*16); load_gate(g1, gsh + 5*16); load_gate(g2, gsh + 10*16);
    gate_high(v, g0); gate_low(v, g1); gate_mid(v, g2);
    if (!side) op1_b0(v, m1);
    store_tile<0>(sv, v, tid); __syncthreads();

    // P4: tile 7-10 — e6 (10,9), e7 (8,7)
    load_tile<7>(sv, v, tid);
    load_gate(g0, gsh + 6*16); load_gate(g1, gsh + 7*16);
    gate_high(v, g0); gate_low(v, g1);
    store_tile<7>(sv, v, tid); __syncthreads();

    // P5: tile 3-6 — e8 (6,5), e9 (4,3)
    load_tile<3>(sv, v, tid);
    load_gate(g0, gsh + 8*16); load_gate(g1, gsh + 9*16);
    gate_high(v, g0); gate_low(v, g1);
    store_tile<3>(sv, v, tid); __syncthreads();

    // P6: tile 8-11 — e11 (11,10), e12 (9,8); right: Q'_b on bit 11
    load_tile<8>(sv, v, tid);
    load_gate(g0, gsh + 11*16); load_gate(g1, gsh + 12*16);
    gate_high(v, g0); gate_low(v, g1);
    if (side) op1_b3(v, m2);
    store_tile<8>(sv, v, tid); __syncthreads();

    // P7: tile 4-7 — e13 (7,6), e14 (5,4)
    load_tile<4>(sv, v, tid);
    load_gate(g0, gsh + 13*16); load_gate(g1, gsh + 14*16);
    gate_high(v, g0); gate_low(v, g1);
    store_tile<4>(sv, v, tid); __syncthreads();

    // P8: tile 0-3 — e15 (3,2), e16 (1,0), then layer-3 e21 (2,1); left: P'_b on bit 0
    load_tile<0>(sv, v, tid);
    load_gate(g0, gsh + 15*16); load_gate(g1, gsh + 16*16); load_gate(g2, gsh + 21*16);
    gate_high(v, g0); gate_low(v, g1); gate_mid(v, g2);
    if (!side) op1_b0(v, m2);
    store_tile<0>(sv, v, tid); __syncthreads();

    // P9: tile 7-10 — e17 (10,9), e18 (8,7)
    load_tile<7>(sv, v, tid);
    load_gate(g0, gsh + 17*16); load_gate(g1, gsh + 18*16);
    gate_high(v, g0); gate_low(v, g1);
    store_tile<7>(sv, v, tid); __syncthreads();

    // P10: tile 3-6 — e19 (6,5), e20 (4,3)
    load_tile<3>(sv, v, tid);
    load_gate(g0, gsh + 19*16); load_gate(g1, gsh + 20*16);
    gate_high(v, g0); gate_low(v, g1);
    store_tile<3>(sv, v, tid); __syncthreads();

    // Final global stores (read through the swizzle).
    const int m = a * 2 + (b >> 1);
    const int p = b & 1;
    if (side == 0) {
#pragma unroll
        for (int t = tid; t < 2048; t += 256) {
            int i = 2 * t + p;
            gLt[i * 8 + m] = sv[swz(i)];
        }
    } else {
#pragma unroll
        for (int j = tid; j < 4096; j += 256)
            gR[(p * 8 + m) * 4096 + j] = sv[swz(j)];
    }
}

// Parity-specialized rank-8 expansion.
// Grid (8, 128), block 256: thread = (col 0..127, par). Tile: 32 i-rows x 512 j.
__global__ void __launch_bounds__(256) k_expand(float4* __restrict__ out)
{
    __shared__ __align__(16) ull sLd[32 * 8];   // L tile rows, {v,v} packs

    const int tid = threadIdx.x;
    const int col = tid & 127;
    const int par = tid >> 7;
    const int jb  = blockIdx.x;     // 0..7
    const int ib  = blockIdx.y;     // 0..127

    {   // load + duplicate L tile (256 floats)
        float vv = gLt[ib * 256 + tid];
        ull pk;
        asm("mov.b64 %0,{%1,%1};" : "=l"(pk) : "f"(vv));
        sLd[tid] = pk;
    }

    // Preload this thread's parity slice of R: 8 x float4 -> 16 packed ulls.
    const float4* gR4 = reinterpret_cast<const float4*>(gR);
    const int jq = jb * 128 + col;
    ull rlo[8], rhi[8];
#pragma unroll
    for (int m = 0; m < 8; ++m) {
        float4 r = gR4[(par * 8 + m) * 1024 + jq];
        asm("mov.b64 %0,{%1,%2};" : "=l"(rlo[m]) : "f"(r.x), "f"(r.y));
        asm("mov.b64 %0,{%1,%2};" : "=l"(rhi[m]) : "f"(r.z), "f"(r.w));
    }
    __syncthreads();

    const ulonglong2* sL2 = reinterpret_cast<const ulonglong2*>(sLd);
#pragma unroll 4
    for (int rr = 0; rr < 16; rr += 2) {
        const int r0 = 2 * rr + par;
        const int r1 = r0 + 2;
        ull a0 = 0ull, a1 = 0ull, b0 = 0ull, b1 = 0ull;
#pragma unroll
        for (int mq = 0; mq < 4; ++mq) {
            ulonglong2 lA = sL2[r0 * 4 + mq];
            ulonglong2 lB = sL2[r1 * 4 + mq];
            asm("fma.rn.f32x2 %0, %1, %2, %0;" : "+l"(a0) : "l"(lA.x), "l"(rlo[2*mq]));
            asm("fma.rn.f32x2 %0, %1, %2, %0;" : "+l"(a1) : "l"(lA.x), "l"(rhi[2*mq]));
            asm("fma.rn.f32x2 %0, %1, %2, %0;" : "+l"(b0) : "l"(lB.x), "l"(rlo[2*mq]));
            asm("fma.rn.f32x2 %0, %1, %2, %0;" : "+l"(b1) : "l"(lB.x), "l"(rhi[2*mq]));
            asm("fma.rn.f32x2 %0, %1, %2, %0;" : "+l"(a0) : "l"(lA.y), "l"(rlo[2*mq+1]));
            asm("fma.rn.f32x2 %0, %1, %2, %0;" : "+l"(a1) : "l"(lA.y), "l"(rhi[2*mq+1]));
            asm("fma.rn.f32x2 %0, %1, %2, %0;" : "+l"(b0) : "l"(lB.y), "l"(rlo[2*mq+1]));
            asm("fma.rn.f32x2 %0, %1, %2, %0;" : "+l"(b1) : "l"(lB.y), "l"(rhi[2*mq+1]));
        }
        float e0, e1, e2, e3, f0, f1, f2, f3;
        asm("mov.b64 {%0,%1}, %2;" : "=f"(e0), "=f"(e1) : "l"(a0));
        asm("mov.b64 {%0,%1}, %2;" : "=f"(e2), "=f"(e3) : "l"(a1));
        asm("mov.b64 {%0,%1}, %2;" : "=f"(f0), "=f"(f1) : "l"(b0));
        asm("mov.b64 {%0,%1}, %2;" : "=f"(f2), "=f"(f3) : "l"(b1));
        out[(ib * 32 + r0) * 1024 + jq] = make_float4(e0, e1, e2, e3);
        out[(ib * 32 + r1) * 1024 + jq] = make_float4(f0, f1, f2, f3);
    }
}

extern "C" void kernel_launch(void* const* d_in, const int* in_sizes, int n_in,
                              void* d_out, int out_size)
{
    const float* states = (const float*)d_in[0];   // (24, 2) f32
    const float* gates  = (const float*)d_in[1];   // (46, 2,2,2,2) f32
    (void)in_sizes; (void)n_in; (void)out_size;

    k_smallsim<<<32, 256>>>(states, gates);
    k_expand<<<dim3(8, 128), 256>>>((float4*)d_out);
}

// round 6
// speedup vs baseline: 1.6036x; 1.0125x over previous
#include <cuda_runtime.h>
#include <cstdint>

typedef unsigned long long ull;

// Rank-16 factors with parity compaction:
//   psi[i*4096 + j] = sum_{m=0..7} Lt[i][m] * R[(i&1)*8 + m][j]
__device__ __align__(16) float gLt[4096 * 8];    // [i][m]
__device__ __align__(16) float gR [16 * 4096];   // [p*8+m][j]

// Gate id schedules per side, ordered by layer then wire.
// e:        0  1  2  3  4  5   6  7  8  9 10   11 12 13 14 15 16   17 18 19 20 21
// b1=10-u: 10  8  6  4  2  0   9  7  5  3  1   10  8  6  4  2  0    9  7  5  3  1
__constant__ short c_Lgi[22] = { 0, 1, 2, 3, 4, 5,  12,13,14,15,16,  23,24,25,26,27,28,  35,36,37,38,39 };
__constant__ short c_Rgi[22] = { 6, 7, 8, 9,10,11,  18,19,20,21,22,  29,30,31,32,33,34,  41,42,43,44,45 };

// Bank-conflict-killing smem swizzle: float-index bits 3,4 ^= bits 7,8.
__device__ __forceinline__ int swz(int i) { return i ^ (((i >> 7) & 3) << 3); }

// ---- packed f32x2 helpers ----
__device__ __forceinline__ ull f2pack(float a, float b) {
    ull r; asm("mov.b64 %0,{%1,%2};" : "=l"(r) : "f"(a), "f"(b)); return r;
}
__device__ __forceinline__ void f2unpack(ull x, float& a, float& b) {
    asm("mov.b64 {%0,%1},%2;" : "=f"(a), "=f"(b) : "l"(x));
}
__device__ __forceinline__ ull f2mul(ull a, ull b) {
    ull r; asm("mul.rn.f32x2 %0,%1,%2;" : "=l"(r) : "l"(a), "l"(b)); return r;
}
__device__ __forceinline__ ull f2fma(ull a, ull b, ull c) {
    ull r; asm("fma.rn.f32x2 %0,%1,%2,%3;" : "=l"(r) : "l"(a), "l"(b), "l"(c)); return r;
}

// Packed 2q butterfly; coefficient roles identical to the scalar R5 version:
//  a' = g0 a + g2 b + g8  c + g10 d   (a=x00, b=i1-toggle, c=i0-toggle, d=both)
__device__ __forceinline__ void bfly2(ull& A, ull& B, ull& C, ull& D, const ull* g) {
    ull x00 = A, x01 = B, x10 = C, x11 = D, t;
    t = f2mul(g[0], x00); t = f2fma(g[2], x01, t); t = f2fma(g[ 8], x10, t); A = f2fma(g[10], x11, t);
    t = f2mul(g[1], x00); t = f2fma(g[3], x01, t); t = f2fma(g[ 9], x10, t); B = f2fma(g[11], x11, t);
    t = f2mul(g[4], x00); t = f2fma(g[6], x01, t); t = f2fma(g[12], x10, t); C = f2fma(g[14], x11, t);
    t = f2mul(g[5], x00); t = f2fma(g[7], x01, t); t = f2fma(g[13], x10, t); D = f2fma(g[15], x11, t);
}
// packed 1q pair: y0' = m0 y0 + m1 y1 ; y1' = m2 y0 + m3 y1
__device__ __forceinline__ void op1p(ull& Y0, ull& Y1, const ull* m) {
    ull y0 = Y0, y1 = Y1, t;
    t = f2mul(m[0], y0); Y0 = f2fma(m[1], y1, t);
    t = f2mul(m[2], y0); Y1 = f2fma(m[3], y1, t);
}

// Packings of the 16-amp tile v[i3 i2 i1 i0]:
//   u[k] = {v[2k], v[2k+1]}   (bit0 packed; u-index bits = v bits 1..3)
//   w[k] = {v[k],  v[k|8]}    (bit3 packed; w-index bits = v bits 0..2)
__device__ __forceinline__ void pack_u(const float* v, ull* u) {
#pragma unroll
    for (int k = 0; k < 8; ++k) u[k] = f2pack(v[2*k], v[2*k+1]);
}
__device__ __forceinline__ void u_to_w(const ull* u, ull* w) {
    float a[16];
#pragma unroll
    for (int k = 0; k < 8; ++k) f2unpack(u[k], a[2*k], a[2*k+1]);
#pragma unroll
    for (int k = 0; k < 8; ++k) w[k] = f2pack(a[k], a[k|8]);
}
__device__ __forceinline__ void unpack_w(const ull* w, float* v) {
#pragma unroll
    for (int k = 0; k < 8; ++k) f2unpack(w[k], v[k], v[k|8]);
}

// gate bits (2,3) on u-packing: groups (u[s], u[s|2], u[s|4], u[s|6]), s=0,1
__device__ __forceinline__ void high_u(ull* u, const ull* g) {
    bfly2(u[0], u[2], u[4], u[6], g);
    bfly2(u[1], u[3], u[5], u[7], g);
}
// gate bits (0,1) on w-packing: groups (w[s], w[s|1], w[s|2], w[s|3]), s=0,4
__device__ __forceinline__ void low_w(ull* w, const ull* g) {
    bfly2(w[0], w[1], w[2], w[3], g);
    bfly2(w[4], w[5], w[6], w[7], g);
}
// gate bits (1,2) on w-packing: groups (w[s], w[s|2], w[s|4], w[s|6]), s=0,1
__device__ __forceinline__ void mid_w(ull* w, const ull* g) {
    bfly2(w[0], w[2], w[4], w[6], g);
    bfly2(w[1], w[3], w[5], w[7], g);
}
// 1q on v-bit3 in u-packing: pairs (u[k], u[k|4]), k=0..3
__device__ __forceinline__ void op1_b3_u(ull* u, const ull* m) {
#pragma unroll
    for (int k = 0; k < 4; ++k) op1p(u[k], u[k|4], m);
}
// 1q on v-bit0 in w-packing: pairs (w[k], w[k|1]), k even
__device__ __forceinline__ void op1_b0_w(ull* w, const ull* m) {
#pragma unroll
    for (int k = 0; k < 8; k += 2) op1p(w[k], w[k+1], m);
}

__device__ __forceinline__ void load_gatep(ull* gp, const ull* gsp) {
#pragma unroll
    for (int c = 0; c < 8; ++c) {
        ulonglong2 t = ((const ulonglong2*)gsp)[c];
        gp[2*c] = t.x; gp[2*c+1] = t.y;
    }
}

// ---- tile exchange through swizzled smem; tile bits T0..T0+3 (unchanged from R5) ----
template<int T0>
__device__ __forceinline__ void store_tile(float* sv, const float* v, int tid) {
    if constexpr (T0 == 0) {
        const int base = tid << 4;
#pragma unroll
        for (int c = 0; c < 4; ++c)
            *(float4*)&sv[swz(base + c*4)] = make_float4(v[4*c], v[4*c+1], v[4*c+2], v[4*c+3]);
    } else {
        const int base = ((tid >> T0) << (T0 + 4)) | (tid & ((1 << T0) - 1));
#pragma unroll
        for (int k = 0; k < 16; ++k) sv[swz(base + (k << T0))] = v[k];
    }
}
template<int T0>
__device__ __forceinline__ void load_tile(const float* sv, float* v, int tid) {
    if constexpr (T0 == 0) {
        const int base = tid << 4;
#pragma unroll
        for (int c = 0; c < 4; ++c) {
            float4 t = *(const float4*)&sv[swz(base + c*4)];
            v[4*c] = t.x; v[4*c+1] = t.y; v[4*c+2] = t.z; v[4*c+3] = t.w;
        }
    } else {
        const int base = ((tid >> T0) << (T0 + 4)) | (tid & ((1 << T0) - 1));
#pragma unroll
        for (int k = 0; k < 16; ++k) v[k] = sv[swz(base + (k << T0))];
    }
}

// 32 blocks: 0..15 -> L_{ab} (k=a*4+b), 16..31 -> R_{ab}. 256 threads, 16 amps each.
__global__ void __launch_bounds__(256) k_smallsim(const float* __restrict__ states,
                                                  const float* __restrict__ gates)
{
    __shared__ __align__(16) float sv[4096];
    __shared__ __align__(16) ull gshp[352];    // packed {g,g} coefficients, 22 gates
    __shared__ float st[24];

    const int tid  = threadIdx.x;
    const int blk  = blockIdx.x;
    const int side = blk >> 4;
    const int k    = blk & 15;
    const int a    = k >> 2;
    const int b    = k & 3;

#pragma unroll
    for (int t = tid; t < 352; t += 256) {
        int e = t >> 4;
        int gi = side ? c_Rgi[e] : c_Lgi[e];
        float val = gates[gi * 16 + (t & 15)];
        gshp[t] = f2pack(val, val);
    }
    if (tid >= 232) st[tid - 232] = states[(side ? 24 : 0) + tid - 232];

    // crossing-gate single-qubit factors, layout m[o*2+i], packed {m,m}
    ull mp1[4], mp2[4];
    {
        float m1[4], m2[4];
        if (side == 0) {
            m1[0]=m1[1]=m1[2]=m1[3]=0.f;  m1[(a & 1)*2 + (a >> 1)] = 1.f;   // P_a on bit 0
            m2[0]=m2[1]=m2[2]=m2[3]=0.f;  m2[(b & 1)*2 + (b >> 1)] = 1.f;   // P'_b on bit 0
        } else {
            const float* g17 = gates + 17*16 + (a >> 1)*8 + (a & 1)*4;       // Q_a on bit 11
            m1[0]=g17[0]; m1[1]=g17[2]; m1[2]=g17[1]; m1[3]=g17[3];
            const float* g40 = gates + 40*16 + (b >> 1)*8 + (b & 1)*4;       // Q'_b on bit 11
            m2[0]=g40[0]; m2[1]=g40[2]; m2[2]=g40[1]; m2[3]=g40[3];
        }
#pragma unroll
        for (int j = 0; j < 4; ++j) { mp1[j] = f2pack(m1[j], m1[j]); mp2[j] = f2pack(m2[j], m2[j]); }
    }
    __syncthreads();

    float v[16];
    ull   u[8], w[8], gp[16], gq[16];

    // Init directly into P1's tile (bits 8..11 local; bits 0..7 = tid).
    {
        float pb = 1.f;
#pragma unroll
        for (int wv = 4; wv < 12; ++wv) pb *= st[2*wv + ((tid >> (11 - wv)) & 1)];
#pragma unroll
        for (int kk = 0; kk < 16; ++kk) {
            float p = pb;
#pragma unroll
            for (int wv = 0; wv < 4; ++wv) p *= st[2*wv + ((kk >> (3 - wv)) & 1)];
            v[kk] = p;
        }
    }

    // P1: tile 8-11 — e0 high, e1 low; right: Q_a on bit 11 (commutes past low: bits {3} vs {0,1})
    pack_u(v, u);
    load_gatep(gp, gshp + 0*16); load_gatep(gq, gshp + 1*16);
    high_u(u, gp);
    if (side) op1_b3_u(u, mp1);
    u_to_w(u, w); low_w(w, gq);
    unpack_w(w, v);
    store_tile<8>(sv, v, tid); __syncthreads();

    // P2: tile 4-7 — e2 high, e3 low
    load_tile<4>(sv, v, tid);  pack_u(v, u);
    load_gatep(gp, gshp + 2*16); load_gatep(gq, gshp + 3*16);
    high_u(u, gp); u_to_w(u, w); low_w(w, gq);
    unpack_w(w, v); store_tile<4>(sv, v, tid); __syncthreads();

    // P3: tile 0-3 — e4 high, e5 low, e10 mid; left: P_a on bit 0
    load_tile<0>(sv, v, tid);  pack_u(v, u);
    load_gatep(gp, gshp + 4*16); load_gatep(gq, gshp + 5*16);
    high_u(u, gp); u_to_w(u, w); low_w(w, gq);
    load_gatep(gp, gshp + 10*16); mid_w(w, gp);
    if (!side) op1_b0_w(w, mp1);
    unpack_w(w, v); store_tile<0>(sv, v, tid); __syncthreads();

    // P4: tile 7-10 — e6 high, e7 low
    load_tile<7>(sv, v, tid);  pack_u(v, u);
    load_gatep(gp, gshp + 6*16); load_gatep(gq, gshp + 7*16);
    high_u(u, gp); u_to_w(u, w); low_w(w, gq);
    unpack_w(w, v); store_tile<7>(sv, v, tid); __syncthreads();

    // P5: tile 3-6 — e8 high, e9 low
    load_tile<3>(sv, v, tid);  pack_u(v, u);
    load_gatep(gp, gshp + 8*16); load_gatep(gq, gshp + 9*16);
    high_u(u, gp); u_to_w(u, w); low_w(w, gq);
    unpack_w(w, v); store_tile<3>(sv, v, tid); __syncthreads();

    // P6: tile 8-11 — e11 high, e12 low; right: Q'_b on bit 11 (commutes with e12..e16)
    load_tile<8>(sv, v, tid);  pack_u(v, u);
    load_gatep(gp, gshp + 11*16); load_gatep(gq, gshp + 12*16);
    high_u(u, gp);
    if (side) op1_b3_u(u, mp2);
    u_to_w(u, w); low_w(w, gq);
    unpack_w(w, v); store_tile<8>(sv, v, tid); __syncthreads();

    // P7: tile 4-7 — e13 high, e14 low
    load_tile<4>(sv, v, tid);  pack_u(v, u);
    load_gatep(gp, gshp + 13*16); load_gatep(gq, gshp + 14*16);
    high_u(u, gp); u_to_w(u, w); low_w(w, gq);
    unpack_w(w, v); store_tile<4>(sv, v, tid); __syncthreads();

    // P8: tile 0-3 — e15 high, e16 low, e21 mid; left: P'_b on bit 0
    load_tile<0>(sv, v, tid);  pack_u(v, u);
    load_gatep(gp, gshp + 15*16); load_gatep(gq, gshp + 16*16);
    high_u(u, gp); u_to_w(u, w); low_w(w, gq);
    load_gatep(gp, gshp + 21*16); mid_w(w, gp);
    if (!side) op1_b0_w(w, mp2);
    unpack_w(w, v); store_tile<0>(sv, v, tid); __syncthreads();

    // P9: tile 7-10 — e17 high, e18 low
    load_tile<7>(sv, v, tid);  pack_u(v, u);
    load_gatep(gp, gshp + 17*16); load_gatep(gq, gshp + 18*16);
    high_u(u, gp); u_to_w(u, w); low_w(w, gq);
    unpack_w(w, v); store_tile<7>(sv, v, tid); __syncthreads();

    // P10: tile 3-6 — e19 high, e20 low
    load_tile<3>(sv, v, tid);  pack_u(v, u);
    load_gatep(gp, gshp + 19*16); load_gatep(gq, gshp + 20*16);
    high_u(u, gp); u_to_w(u, w); low_w(w, gq);
    unpack_w(w, v); store_tile<3>(sv, v, tid); __syncthreads();

    // Final global stores (read through the swizzle).
    const int mm = a * 2 + (b >> 1);
    const int p  = b & 1;
    if (side == 0) {
#pragma unroll
        for (int t = tid; t < 2048; t += 256) {
            int i = 2 * t + p;
            gLt[i * 8 + mm] = sv[swz(i)];
        }
    } else {
#pragma unroll
        for (int j = tid; j < 4096; j += 256)
            gR[(p * 8 + mm) * 4096 + j] = sv[swz(j)];
    }
}

// One ib-tile of the parity-specialized rank-8 expansion.
__device__ __forceinline__ void expand_tile(const ull* sLbuf, const ull* rlo, const ull* rhi,
                                            float4* __restrict__ out, int ib, int jq, int par)
{
    const ulonglong2* sL2 = reinterpret_cast<const ulonglong2*>(sLbuf);
#pragma unroll 4
    for (int rr = 0; rr < 16; rr += 2) {
        const int r0 = 2 * rr + par;
        const int r1 = r0 + 2;
        ull a0 = 0ull, a1 = 0ull, b0 = 0ull, b1 = 0ull;
#pragma unroll
        for (int mq = 0; mq < 4; ++mq) {
            ulonglong2 lA = sL2[r0 * 4 + mq];
            ulonglong2 lB = sL2[r1 * 4 + mq];
            asm("fma.rn.f32x2 %0, %1, %2, %0;" : "+l"(a0) : "l"(lA.x), "l"(rlo[2*mq]));
            asm("fma.rn.f32x2 %0, %1, %2, %0;" : "+l"(a1) : "l"(lA.x), "l"(rhi[2*mq]));
            asm("fma.rn.f32x2 %0, %1, %2, %0;" : "+l"(b0) : "l"(lB.x), "l"(rlo[2*mq]));
            asm("fma.rn.f32x2 %0, %1, %2, %0;" : "+l"(b1) : "l"(lB.x), "l"(rhi[2*mq]));
            asm("fma.rn.f32x2 %0, %1, %2, %0;" : "+l"(a0) : "l"(lA.y), "l"(rlo[2*mq+1]));
            asm("fma.rn.f32x2 %0, %1, %2, %0;" : "+l"(a1) : "l"(lA.y), "l"(rhi[2*mq+1]));
            asm("fma.rn.f32x2 %0, %1, %2, %0;" : "+l"(b0) : "l"(lB.y), "l"(rlo[2*mq+1]));
            asm("fma.rn.f32x2 %0, %1, %2, %0;" : "+l"(b1) : "l"(lB.y), "l"(rhi[2*mq+1]));
        }
        float e0, e1, e2, e3, f0, f1, f2, f3;
        asm("mov.b64 {%0,%1}, %2;" : "=f"(e0), "=f"(e1) : "l"(a0));
        asm("mov.b64 {%0,%1}, %2;" : "=f"(e2), "=f"(e3) : "l"(a1));
        asm("mov.b64 {%0,%1}, %2;" : "=f"(f0), "=f"(f1) : "l"(b0));
        asm("mov.b64 {%0,%1}, %2;" : "=f"(f2), "=f"(f3) : "l"(b1));
        out[(ib * 32 + r0) * 1024 + jq] = make_float4(e0, e1, e2, e3);
        out[(ib * 32 + r1) * 1024 + jq] = make_float4(f0, f1, f2, f3);
    }
}

// Grid (8, 64), block 256. Thread = (col, par); R regs reused across 2 ib-tiles.
// Single wave at 4 blocks/SM (512 <= 592).
__global__ void __launch_bounds__(256, 4) k_expand(float4* __restrict__ out)
{
    __shared__ __align__(16) ull sLd[2][256];

    const int tid = threadIdx.x;
    const int col = tid & 127;
    const int par = tid >> 7;
    const int jb  = blockIdx.x;     // 0..7
    const int by  = blockIdx.y;     // 0..63 -> ib = 2*by, 2*by+1
    const int jq  = jb * 128 + col;

    // L tile 0 into smem; prefetch tile 1 into a register.
    float l0 = gLt[(2*by + 0) * 256 + tid];
    float l1 = gLt[(2*by + 1) * 256 + tid];
    sLd[0][tid] = f2pack(l0, l0);

    // R preload: this thread's parity slice, once per block (reused for both tiles).
    const float4* gR4 = reinterpret_cast<const float4*>(gR);
    ull rlo[8], rhi[8];
#pragma unroll
    for (int m = 0; m < 8; ++m) {
        float4 r = gR4[(par * 8 + m) * 1024 + jq];
        rlo[m] = f2pack(r.x, r.y);
        rhi[m] = f2pack(r.z, r.w);
    }
    __syncthreads();

    expand_tile(sLd[0], rlo, rhi, out, 2*by + 0, jq, par);

    sLd[1][tid] = f2pack(l1, l1);   // writes disjoint from sLd[0] reads: no pre-bar needed
    __syncthreads();

    expand_tile(sLd[1], rlo, rhi, out, 2*by + 1, jq, par);
}

extern "C" void kernel_launch(void* const* d_in, const int* in_sizes, int n_in,
                              void* d_out, int out_size)
{
    const float* states = (const float*)d_in[0];   // (24, 2) f32
    const float* gates  = (const float*)d_in[1];   // (46, 2,2,2,2) f32
    (void)in_sizes; (void)n_in; (void)out_size;

    k_smallsim<<<32, 256>>>(states, gates);
    k_expand<<<dim3(8, 64), 256>>>((float4*)d_out);
}